// round 1
// baseline (speedup 1.0000x reference)
#include <cuda_runtime.h>

#define D_ 160
#define H_ 192
#define W_ 160
#define HW_ (H_ * W_)
#define N_ (D_ * H_ * W_)          // 4,915,200
#define R_ 4                        // window radius (9 taps)
#define WSZ 729.0f
#define DCHUNK 32
#define GRID3X (HW_ / 256)          // 120
#define GRID3Y (D_ / DCHUNK)        // 5
#define NPART3 (GRID3X * GRID3Y)    // 600
#define GRID4 1024

// Scratch (static device globals — allocation-free per harness rules)
__device__ float g_A[5u * N_];      // after W-pass: I,J,I2,J2,IJ box-summed along W
__device__ float g_B[5u * N_];      // after H-pass
__device__ float g_ccpart[NPART3];
__device__ float g_gpart[GRID4 * 3];

// ---------------------------------------------------------------------------
// Pass 1: compute the 5 products on the fly and box-sum along W (contiguous).
// One block per (d,h) row, 160 threads, shared-memory row with zero padding.
// ---------------------------------------------------------------------------
__global__ void k_boxW(const float* __restrict__ I, const float* __restrict__ J)
{
    __shared__ float sI[W_ + 2 * R_];
    __shared__ float sJ[W_ + 2 * R_];
    const int row = blockIdx.x;            // 0 .. D*H-1
    const int w   = threadIdx.x;           // 0 .. 159
    const int base = row * W_;

    sI[w + R_] = I[base + w];
    sJ[w + R_] = J[base + w];
    if (w < R_) {
        sI[w] = 0.f; sJ[w] = 0.f;
        sI[w + W_ + R_] = 0.f; sJ[w + W_ + R_] = 0.f;
    }
    __syncthreads();

    float s1 = 0.f, s2 = 0.f, s3 = 0.f, s4 = 0.f, s5 = 0.f;
#pragma unroll
    for (int k = 0; k < 2 * R_ + 1; k++) {
        float a = sI[w + k];
        float b = sJ[w + k];
        s1 += a;         // I
        s2 += b;         // J
        s3 += a * a;     // I*I
        s4 += b * b;     // J*J
        s5 += a * b;     // I*J
    }
    const int idx = base + w;
    g_A[0u * N_ + idx] = s1;
    g_A[1u * N_ + idx] = s2;
    g_A[2u * N_ + idx] = s3;
    g_A[3u * N_ + idx] = s4;
    g_A[4u * N_ + idx] = s5;
}

// ---------------------------------------------------------------------------
// Pass 2: box-sum along H via running window. grid = (D, 5ch), block = W.
// Coalesced across w. The trailing-edge re-read is an L1 hit.
// ---------------------------------------------------------------------------
__global__ void k_boxH()
{
    const int w = threadIdx.x;
    const int d = blockIdx.x;
    const int c = blockIdx.y;
    const float* __restrict__ p = g_A + (size_t)c * N_ + d * HW_ + w;
    float*       __restrict__ q = g_B + (size_t)c * N_ + d * HW_ + w;

    float S = 0.f;
#pragma unroll
    for (int h = 0; h < R_; h++) S += p[h * W_];   // sum h=0..3

    for (int h = 0; h < H_; h++) {
        int hn = h + R_;
        if (hn < H_) S += p[hn * W_];
        q[h * W_] = S;
        int hp = h - R_;
        if (hp >= 0) S -= p[hp * W_];
    }
}

// ---------------------------------------------------------------------------
// Pass 3: box-sum along D (running window, 5 channels) fused with the
// LNCC cc formula and a block reduction of sum(cc).
// grid = (HW/256, D/DCHUNK), block = 256. Threads map to (h,w) flat index.
// ---------------------------------------------------------------------------
__global__ void k_boxD_cc()
{
    const int hw = blockIdx.x * 256 + threadIdx.x;   // 0 .. HW-1
    const int d0 = blockIdx.y * DCHUNK;

    float S[5];
#pragma unroll
    for (int c = 0; c < 5; c++) {
        const float* __restrict__ p = g_B + (size_t)c * N_ + hw;
        float s = 0.f;
#pragma unroll
        for (int dd = d0 - R_; dd < d0 + R_; dd++)
            if (dd >= 0 && dd < D_) s += p[dd * HW_];
        S[c] = s;
    }

    float acc = 0.f;
    for (int d = d0; d < d0 + DCHUNK; d++) {
        const int dn = d + R_;
        if (dn < D_) {
#pragma unroll
            for (int c = 0; c < 5; c++)
                S[c] += g_B[(size_t)c * N_ + dn * HW_ + hw];
        }
        // cc at voxel (d, h, w)
        const float I_sum = S[0], J_sum = S[1];
        const float I2s = S[2], J2s = S[3], IJs = S[4];
        const float uI = I_sum * (1.0f / WSZ);
        const float uJ = J_sum * (1.0f / WSZ);
        const float cross = IJs - uJ * I_sum - uI * J_sum + uI * uJ * WSZ;
        const float Iv = I2s - 2.0f * uI * I_sum + uI * uI * WSZ;
        const float Jv = J2s - 2.0f * uJ * J_sum + uJ * uJ * WSZ;
        acc += cross * cross / (Iv * Jv + 1e-5f);

        const int dp = d - R_;
        if (dp >= 0) {
#pragma unroll
            for (int c = 0; c < 5; c++)
                S[c] -= g_B[(size_t)c * N_ + dp * HW_ + hw];
        }
    }

    __shared__ float sh[256];
    const int t = threadIdx.x;
    sh[t] = acc;
    __syncthreads();
#pragma unroll
    for (int s = 128; s > 0; s >>= 1) {
        if (t < s) sh[t] += sh[t + s];
        __syncthreads();
    }
    if (t == 0) g_ccpart[blockIdx.y * GRID3X + blockIdx.x] = sh[0];
}

// ---------------------------------------------------------------------------
// Gradient (smoothness) loss partials over the 3-channel displacement field.
// ---------------------------------------------------------------------------
__global__ void k_grad(const float* __restrict__ s)
{
    float aH = 0.f, aD = 0.f, aW = 0.f;
    const int total = 3 * N_;
    for (int i = blockIdx.x * blockDim.x + threadIdx.x; i < total;
         i += gridDim.x * blockDim.x) {
        const int rem = i % N_;
        const int w = rem % W_;
        const int h = (rem / W_) % H_;
        const int d = rem / HW_;
        const float v = s[i];
        if (h < H_ - 1) { float t = s[i + W_]  - v; aH += t * t; }
        if (d < D_ - 1) { float t = s[i + HW_] - v; aD += t * t; }
        if (w < W_ - 1) { float t = s[i + 1]   - v; aW += t * t; }
    }

    __shared__ float sh[3][256];
    const int t = threadIdx.x;
    sh[0][t] = aH; sh[1][t] = aD; sh[2][t] = aW;
    __syncthreads();
#pragma unroll
    for (int st = 128; st > 0; st >>= 1) {
        if (t < st) {
            sh[0][t] += sh[0][t + st];
            sh[1][t] += sh[1][t + st];
            sh[2][t] += sh[2][t + st];
        }
        __syncthreads();
    }
    if (t == 0) {
        g_gpart[blockIdx.x * 3 + 0] = sh[0][0];
        g_gpart[blockIdx.x * 3 + 1] = sh[1][0];
        g_gpart[blockIdx.x * 3 + 2] = sh[2][0];
    }
}

// ---------------------------------------------------------------------------
// Final deterministic combine (fixed-order reduction, no atomics).
// ---------------------------------------------------------------------------
__global__ void k_final(float* __restrict__ out)
{
    __shared__ float shcc[256];
    __shared__ float shg[256];
    const int t = threadIdx.x;

    float cc = 0.f;
    for (int i = t; i < NPART3; i += 256) cc += g_ccpart[i];

    // count of diff elements along each axis (incl. 3 channels)
    const float invNH = 1.0f / (3.0f * D_ * (H_ - 1) * W_);
    const float invND = 1.0f / (3.0f * (D_ - 1) * H_ * W_);
    const float invNW = 1.0f / (3.0f * D_ * H_ * (W_ - 1));

    float g = 0.f;
    for (int i = t; i < GRID4; i += 256) {
        g += g_gpart[i * 3 + 0] * invNH
           + g_gpart[i * 3 + 1] * invND
           + g_gpart[i * 3 + 2] * invNW;
    }

    shcc[t] = cc;
    shg[t] = g;
    __syncthreads();
#pragma unroll
    for (int s = 128; s > 0; s >>= 1) {
        if (t < s) { shcc[t] += shcc[t + s]; shg[t] += shg[t + s]; }
        __syncthreads();
    }
    if (t == 0) {
        const float lncc = 1.0f - shcc[0] / (float)N_;
        out[0] = lncc + 0.01f * (shg[0] / 3.0f);
    }
}

extern "C" void kernel_launch(void* const* d_in, const int* in_sizes, int n_in,
                              void* d_out, int out_size)
{
    const float* I   = (const float*)d_in[0];   // y_fwd
    const float* J   = (const float*)d_in[1];   // y_inv
    const float* dsp = (const float*)d_in[2];   // dsp_fields (3 channels)
    float* out = (float*)d_out;

    k_boxW<<<D_ * H_, W_>>>(I, J);
    k_boxH<<<dim3(D_, 5), W_>>>();
    k_boxD_cc<<<dim3(GRID3X, GRID3Y), 256>>>();
    k_grad<<<GRID4, 256>>>(dsp);
    k_final<<<1, 256>>>(out);
}

// round 2
// speedup vs baseline: 1.7244x; 1.7244x over previous
#include <cuda_runtime.h>

#define D_ 160
#define H_ 192
#define W_ 160
#define HW_ (H_ * W_)
#define N_ (D_ * H_ * W_)          // 4,915,200
#define R_ 4                        // window radius (9 taps)
#define WSZ 729.0f
#define DCHUNK 32
#define GRID3X (HW_ / 256)          // 120
#define GRID3Y (D_ / DCHUNK)        // 5
#define NPART3 (GRID3X * GRID3Y)    // 600
#define GRID4 1024
#define HCHUNK 48                   // output rows per block in fused WH pass
#define NHCH (H_ / HCHUNK)          // 4

// Scratch (static device globals — allocation-free per harness rules)
__device__ float g_B[5u * N_];      // after fused W+H pass: 5 channels box-summed in W,H
__device__ float g_ccpart[NPART3];
__device__ float g_gpart[GRID4 * 3];

// ---------------------------------------------------------------------------
// Fused Pass 1+2: compute I,J,I2,J2,IJ on the fly, box-sum along W (9-tap via
// smem row), then box-sum along H with a running window backed by a 9-row
// ring buffer in smem. Writes g_B directly (g_A eliminated).
// grid = (D, H/HCHUNK), block = W (160 threads).
// ---------------------------------------------------------------------------
__global__ void k_boxWH(const float* __restrict__ I, const float* __restrict__ J)
{
    __shared__ float ring[9][5][W_];       // per-thread columns, conflict-free
    __shared__ float sI[W_ + 2 * R_];
    __shared__ float sJ[W_ + 2 * R_];

    const int d  = blockIdx.x;
    const int h0 = blockIdx.y * HCHUNK;
    const int w  = threadIdx.x;

    if (w < R_) {                           // zero halos once
        sI[w] = 0.f; sJ[w] = 0.f;
        sI[W_ + R_ + w] = 0.f; sJ[W_ + R_ + w] = 0.f;
    }

    const float* __restrict__ Ib = I + (size_t)d * HW_;
    const float* __restrict__ Jb = J + (size_t)d * HW_;

    float S0 = 0.f, S1 = 0.f, S2 = 0.f, S3 = 0.f, S4 = 0.f;

    for (int h = h0 - R_; h < h0 + HCHUNK + R_; h++) {
        __syncthreads();                    // prior readers of sI/sJ done
        const bool valid = (h >= 0) & (h < H_);
        if (valid) {
            sI[w + R_] = Ib[h * W_ + w];
            sJ[w + R_] = Jb[h * W_ + w];
        }
        __syncthreads();

        float ws0 = 0.f, ws1 = 0.f, ws2 = 0.f, ws3 = 0.f, ws4 = 0.f;
        if (valid) {
#pragma unroll
            for (int k = 0; k < 2 * R_ + 1; k++) {
                float a = sI[w + k];
                float b = sJ[w + k];
                ws0 += a; ws1 += b;
                ws2 += a * a; ws3 += b * b; ws4 += a * b;
            }
        }
        const int slot = (h + 18) % 9;
        ring[slot][0][w] = ws0; S0 += ws0;
        ring[slot][1][w] = ws1; S1 += ws1;
        ring[slot][2][w] = ws2; S2 += ws2;
        ring[slot][3][w] = ws3; S3 += ws3;
        ring[slot][4][w] = ws4; S4 += ws4;

        const int ho = h - R_;
        if (ho >= h0 && ho < h0 + HCHUNK) {
            const size_t o = (size_t)d * HW_ + ho * W_ + w;
            g_B[0u * N_ + o] = S0;
            g_B[1u * N_ + o] = S1;
            g_B[2u * N_ + o] = S2;
            g_B[3u * N_ + o] = S3;
            g_B[4u * N_ + o] = S4;
        }
        const int hl = h - 2 * R_;          // row leaving the 9-row window
        if (hl >= h0 - R_) {
            const int ls = (hl + 18) % 9;
            S0 -= ring[ls][0][w];
            S1 -= ring[ls][1][w];
            S2 -= ring[ls][2][w];
            S3 -= ring[ls][3][w];
            S4 -= ring[ls][4][w];
        }
    }
}

// ---------------------------------------------------------------------------
// Pass 3: box-sum along D (running window, 5 channels) fused with the
// LNCC cc formula and a block reduction of sum(cc).
// ---------------------------------------------------------------------------
__global__ void k_boxD_cc()
{
    const int hw = blockIdx.x * 256 + threadIdx.x;   // 0 .. HW-1
    const int d0 = blockIdx.y * DCHUNK;

    float S[5];
#pragma unroll
    for (int c = 0; c < 5; c++) {
        const float* __restrict__ p = g_B + (size_t)c * N_ + hw;
        float s = 0.f;
#pragma unroll
        for (int dd = d0 - R_; dd < d0 + R_; dd++)
            if (dd >= 0 && dd < D_) s += p[dd * HW_];
        S[c] = s;
    }

    float acc = 0.f;
    for (int d = d0; d < d0 + DCHUNK; d++) {
        const int dn = d + R_;
        if (dn < D_) {
#pragma unroll
            for (int c = 0; c < 5; c++)
                S[c] += g_B[(size_t)c * N_ + dn * HW_ + hw];
        }
        const float I_sum = S[0], J_sum = S[1];
        const float I2s = S[2], J2s = S[3], IJs = S[4];
        const float uI = I_sum * (1.0f / WSZ);
        const float uJ = J_sum * (1.0f / WSZ);
        const float cross = IJs - uJ * I_sum - uI * J_sum + uI * uJ * WSZ;
        const float Iv = I2s - 2.0f * uI * I_sum + uI * uI * WSZ;
        const float Jv = J2s - 2.0f * uJ * J_sum + uJ * uJ * WSZ;
        acc += cross * cross / (Iv * Jv + 1e-5f);

        const int dp = d - R_;
        if (dp >= 0) {
#pragma unroll
            for (int c = 0; c < 5; c++)
                S[c] -= g_B[(size_t)c * N_ + dp * HW_ + hw];
        }
    }

    __shared__ float sh[256];
    const int t = threadIdx.x;
    sh[t] = acc;
    __syncthreads();
#pragma unroll
    for (int s = 128; s > 0; s >>= 1) {
        if (t < s) sh[t] += sh[t + s];
        __syncthreads();
    }
    if (t == 0) g_ccpart[blockIdx.y * GRID3X + blockIdx.x] = sh[0];
}

// ---------------------------------------------------------------------------
// Gradient loss, float4-vectorized: 4 elements per index-decode, dx mostly
// in-register. W=160 divisible by 4 so vectors never cross rows.
// ---------------------------------------------------------------------------
__global__ void k_grad(const float* __restrict__ s)
{
    const int W4 = W_ / 4;                  // 40
    const int NV = N_ / 4;                  // vectors per channel
    const int total = 3 * NV;
    const float4* __restrict__ p4 = (const float4*)s;
    const float*  __restrict__ pf = s;

    float aH = 0.f, aD = 0.f, aW = 0.f;
    for (int i = blockIdx.x * blockDim.x + threadIdx.x; i < total;
         i += gridDim.x * blockDim.x) {
        const int r  = i % NV;              // vector index within channel
        const int wv = r % W4;
        const int h  = (r / W4) % H_;
        const int d  = r / (W4 * H_);

        const float4 v = p4[i];
        float t;
        t = v.y - v.x; aW += t * t;
        t = v.z - v.y; aW += t * t;
        t = v.w - v.z; aW += t * t;
        if (wv < W4 - 1) { t = pf[i * 4 + 4] - v.w; aW += t * t; }
        if (h < H_ - 1) {
            const float4 u = p4[i + W4];
            t = u.x - v.x; aH += t * t;
            t = u.y - v.y; aH += t * t;
            t = u.z - v.z; aH += t * t;
            t = u.w - v.w; aH += t * t;
        }
        if (d < D_ - 1) {
            const float4 u = p4[i + HW_ / 4];
            t = u.x - v.x; aD += t * t;
            t = u.y - v.y; aD += t * t;
            t = u.z - v.z; aD += t * t;
            t = u.w - v.w; aD += t * t;
        }
    }

    __shared__ float sh[3][256];
    const int t2 = threadIdx.x;
    sh[0][t2] = aH; sh[1][t2] = aD; sh[2][t2] = aW;
    __syncthreads();
#pragma unroll
    for (int st = 128; st > 0; st >>= 1) {
        if (t2 < st) {
            sh[0][t2] += sh[0][t2 + st];
            sh[1][t2] += sh[1][t2 + st];
            sh[2][t2] += sh[2][t2 + st];
        }
        __syncthreads();
    }
    if (t2 == 0) {
        g_gpart[blockIdx.x * 3 + 0] = sh[0][0];
        g_gpart[blockIdx.x * 3 + 1] = sh[1][0];
        g_gpart[blockIdx.x * 3 + 2] = sh[2][0];
    }
}

// ---------------------------------------------------------------------------
// Final deterministic combine.
// ---------------------------------------------------------------------------
__global__ void k_final(float* __restrict__ out)
{
    __shared__ float shcc[256];
    __shared__ float shg[256];
    const int t = threadIdx.x;

    float cc = 0.f;
    for (int i = t; i < NPART3; i += 256) cc += g_ccpart[i];

    const float invNH = 1.0f / (3.0f * D_ * (H_ - 1) * W_);
    const float invND = 1.0f / (3.0f * (D_ - 1) * H_ * W_);
    const float invNW = 1.0f / (3.0f * D_ * H_ * (W_ - 1));

    float g = 0.f;
    for (int i = t; i < GRID4; i += 256) {
        g += g_gpart[i * 3 + 0] * invNH
           + g_gpart[i * 3 + 1] * invND
           + g_gpart[i * 3 + 2] * invNW;
    }

    shcc[t] = cc;
    shg[t] = g;
    __syncthreads();
#pragma unroll
    for (int s = 128; s > 0; s >>= 1) {
        if (t < s) { shcc[t] += shcc[t + s]; shg[t] += shg[t + s]; }
        __syncthreads();
    }
    if (t == 0) {
        const float lncc = 1.0f - shcc[0] / (float)N_;
        out[0] = lncc + 0.01f * (shg[0] / 3.0f);
    }
}

extern "C" void kernel_launch(void* const* d_in, const int* in_sizes, int n_in,
                              void* d_out, int out_size)
{
    const float* I   = (const float*)d_in[0];   // y_fwd
    const float* J   = (const float*)d_in[1];   // y_inv
    const float* dsp = (const float*)d_in[2];   // dsp_fields (3 channels)
    float* out = (float*)d_out;

    k_boxWH<<<dim3(D_, NHCH), W_>>>(I, J);
    k_boxD_cc<<<dim3(GRID3X, GRID3Y), 256>>>();
    k_grad<<<GRID4, 256>>>(dsp);
    k_final<<<1, 256>>>(out);
}